// round 11
// baseline (speedup 1.0000x reference)
#include <cuda_runtime.h>
#include <cstdint>

#define GMAX 64
#define BMAX 64
#define ANCH 2
#define NTHR 128

// Precomputed per-batch compacted GT tables (written by prep kernel)
__device__ float4 g_box [BMAX * GMAX];
__device__ float4 g_meta[BMAX * GMAX];
__device__ __align__(16) float g_area[BMAX * GMAX];
__device__ float  g_cls [BMAX * GMAX];
__device__ int    g_cnt [BMAX];

// ---------------- Kernel 1: one warp per batch, order-preserving compaction ----------------
__global__ void ssd_prep_kernel(const float* __restrict__ gt,
                                const int*   __restrict__ cls)
{
    const int b    = blockIdx.x;
    const int lane = threadIdx.x & 31;
    const int gbase = b * GMAX;

    int cnt = 0;
    #pragma unroll
    for (int chunk = 0; chunk < GMAX / 32; ++chunk) {
        const int g = chunk * 32 + lane;
        const float* gp = gt + (size_t)(gbase + g) * 5;
        float y1 = gp[0], x1 = gp[1], y2 = gp[2], x2 = gp[3], tg = gp[4];
        bool valid = (tg != 0.0f);
        unsigned m = __ballot_sync(0xffffffffu, valid);
        int pos = cnt + __popc(m & ((1u << lane) - 1u));
        if (valid) {
            g_box [gbase + pos] = make_float4(y1, x1, y2, x2);
            g_area[gbase + pos] = __fmul_rn(__fsub_rn(x2, x1), __fsub_rn(y2, y1));
            g_meta[gbase + pos] = make_float4((y2 + y1) * 0.5f, (x2 + x1) * 0.5f,
                                              __log2f(y2 - y1), __log2f(x2 - x1));
            g_cls [gbase + pos] = (float)cls[(size_t)(gbase + g) * 2];
        }
        cnt += __popc(m);
    }
    if (lane == 0 && cnt == 0) {
        // reference: argmax over all -1 == index 0; deltas built from raw gt[0]
        const float* gp = gt + (size_t)gbase * 5;
        float y1 = gp[0], x1 = gp[1], y2 = gp[2], x2 = gp[3];
        g_box [gbase] = make_float4(y1, x1, y2, x2);
        g_area[gbase] = __fmul_rn(__fsub_rn(x2, x1), __fsub_rn(y2, y1));
        g_meta[gbase] = make_float4((y2 + y1) * 0.5f, (x2 + x1) * 0.5f,
                                    __log2f(y2 - y1), __log2f(x2 - x1));
        g_cls [gbase] = (float)cls[(size_t)gbase * 2];
    }
    // pad to multiple of 4 with never-win dummies (inter==0, area==0)
    const int cnt_eff = (cnt == 0) ? 1 : cnt;
    const int cnt_pad = (cnt_eff + 3) & ~3;
    if (lane < cnt_pad - cnt_eff) {
        const int p = gbase + cnt_eff + lane;
        g_box [p] = make_float4(0.0f, 0.0f, 0.0f, 0.0f);
        g_area[p] = 0.0f;
        g_cls [p] = 0.0f;
        g_meta[p] = make_float4(0.0f, 0.0f, 0.0f, 0.0f);
    }
    if (lane == 0) g_cnt[b] = cnt_pad;
}

// ---------------- Kernel 2: main — loop prologue is a plain table copy ----------------
__global__ void __launch_bounds__(NTHR, 12)
ssd_target_kernel(const float* __restrict__ anchors,
                  float*       __restrict__ out,
                  int B, int A)
{
    __shared__ float4 s_box [GMAX];
    __shared__ float4 s_meta[GMAX];
    __shared__ __align__(16) float s_area[GMAX];
    __shared__ float  s_cls [GMAX];
    __shared__ int    s_cnt;

    const int b = blockIdx.y;
    // cooperative copy: threads 0-63 box+area, threads 64-127 meta+cls
    if (threadIdx.x < GMAX) {
        const int t = threadIdx.x;
        s_box [t] = g_box [b * GMAX + t];
        s_area[t] = g_area[b * GMAX + t];
    } else {
        const int t = threadIdx.x - GMAX;
        s_meta[t] = g_meta[b * GMAX + t];
        s_cls [t] = g_cls [b * GMAX + t];
        if (t == 0) s_cnt = g_cnt[b];
    }
    __syncthreads();

    const int a0 = blockIdx.x * (NTHR * ANCH) + threadIdx.x;
    const int a1 = a0 + NTHR;
    if (a0 >= A) return;
    const bool has1 = (a1 < A);

    const float4 an0 = __ldg(reinterpret_cast<const float4*>(anchors) + a0);
    const float4 an1 = has1 ? __ldg(reinterpret_cast<const float4*>(anchors) + a1) : an0;
    const float area0 = __fmul_rn(__fsub_rn(an0.w, an0.y), __fsub_rn(an0.z, an0.x));
    const float area1 = __fmul_rn(__fsub_rn(an1.w, an1.y), __fsub_rn(an1.z, an1.x));

    const int cntp = s_cnt;

    // Division/union-free argmax:
    //   iou_j > iou_b  <=>  inter_j * S_b > inter_b * S_j,  S = area_gt + area_an
    // max(0,x)==__saturatef(x) (extents < 1 -> .SAT folds into the FADD).
    // Dummies (inter=0, area=0) never beat a real entry; real entry 0 beats
    // the -1 sentinel even at inter==0.
    float bi0 = -1.0f, bS0 = 0.0f; int bj0 = 0;   // sentinel: iou = -1/(0-(-1)) = -1
    float bi1 = -1.0f, bS1 = 0.0f; int bj1 = 0;

    #define PAIR(g4, ag, jj)                                                        \
        {                                                                           \
            float iw0 = __saturatef(__fsub_rn(fminf((g4).w, an0.w),                 \
                                              fmaxf((g4).y, an0.y)));               \
            float ih0 = __saturatef(__fsub_rn(fminf((g4).z, an0.z),                 \
                                              fmaxf((g4).x, an0.x)));               \
            float in0 = __fmul_rn(iw0, ih0);                                        \
            float Sv0 = __fadd_rn((ag), area0);                                     \
            bool bt0 = __fmul_rn(in0, bS0) > __fmul_rn(bi0, Sv0);                   \
            bi0 = bt0 ? in0 : bi0;  bS0 = bt0 ? Sv0 : bS0;  bj0 = bt0 ? (jj) : bj0; \
            float iw1 = __saturatef(__fsub_rn(fminf((g4).w, an1.w),                 \
                                              fmaxf((g4).y, an1.y)));               \
            float ih1 = __saturatef(__fsub_rn(fminf((g4).z, an1.z),                 \
                                              fmaxf((g4).x, an1.x)));               \
            float in1 = __fmul_rn(iw1, ih1);                                        \
            float Sv1 = __fadd_rn((ag), area1);                                     \
            bool bt1 = __fmul_rn(in1, bS1) > __fmul_rn(bi1, Sv1);                   \
            bi1 = bt1 ? in1 : bi1;  bS1 = bt1 ? Sv1 : bS1;  bj1 = bt1 ? (jj) : bj1; \
        }

    for (int j = 0; j < cntp; j += 4) {     // cntp multiple of 4: no remainder
        const float4 a4 = *reinterpret_cast<const float4*>(s_area + j);
        const float4 g0 = s_box[j + 0];
        const float4 g1 = s_box[j + 1];
        const float4 g2 = s_box[j + 2];
        const float4 g3 = s_box[j + 3];
        PAIR(g0, a4.x, j + 0)
        PAIR(g1, a4.y, j + 1)
        PAIR(g2, a4.z, j + 2)
        PAIR(g3, a4.w, j + 3)
    }
    #undef PAIR

    const int N = B * A;
    float4* out4 = reinterpret_cast<float4*>(out);  // deltas  [0, 4N)
    float*  outc = out + 4 * (size_t)N;             // classes [4N, 5N)
    float*  outt = out + 5 * (size_t)N;             // tags    [5N, 6N)
    const float KLOG = 3.4657359027997265f;         // ln(2)/0.2 (folds /0.2 BBOX_STD)
    const int row = b * A;

    // ---- epilogue anchor 0 (tag path exact; delta path fast-approx, tol 1e-3) ----
    {
        const float iou_max = __fdiv_rn(bi0, __fsub_rn(bS0, bi0)); // u = S - inter
        const float tagv = (iou_max >= 0.5f) ? 1.0f
                          : ((iou_max < 0.4f) ? -1.0f : 0.0f);
        const float4 mt = s_meta[bj0];
        const float ah = an0.z - an0.x, aw = an0.w - an0.y;
        const float acy = (an0.z + an0.x) * 0.5f, acx = (an0.w + an0.y) * 0.5f;
        const float dy = (mt.x - acy) * __fdividef(10.0f, ah);
        const float dx = (mt.y - acx) * __fdividef(10.0f, aw);
        const float dh = (mt.z - __log2f(ah)) * KLOG;
        const float dw = (mt.w - __log2f(aw)) * KLOG;
        const int idx = row + a0;
        out4[idx] = make_float4(dy, dx, dh, dw);
        outc[idx] = s_cls[bj0];
        outt[idx] = tagv;
    }
    // ---- epilogue anchor 1 ----
    if (has1) {
        const float iou_max = __fdiv_rn(bi1, __fsub_rn(bS1, bi1));
        const float tagv = (iou_max >= 0.5f) ? 1.0f
                          : ((iou_max < 0.4f) ? -1.0f : 0.0f);
        const float4 mt = s_meta[bj1];
        const float ah = an1.z - an1.x, aw = an1.w - an1.y;
        const float acy = (an1.z + an1.x) * 0.5f, acx = (an1.w + an1.y) * 0.5f;
        const float dy = (mt.x - acy) * __fdividef(10.0f, ah);
        const float dx = (mt.y - acx) * __fdividef(10.0f, aw);
        const float dh = (mt.z - __log2f(ah)) * KLOG;
        const float dw = (mt.w - __log2f(aw)) * KLOG;
        const int idx = row + a1;
        out4[idx] = make_float4(dy, dx, dh, dw);
        outc[idx] = s_cls[bj1];
        outt[idx] = tagv;
    }
}

extern "C" void kernel_launch(void* const* d_in, const int* in_sizes, int n_in,
                              void* d_out, int out_size)
{
    const float* gt      = (const float*)d_in[0];   // [B, 64, 5]
    const int*   cls     = (const int*)  d_in[1];   // [B, 64, 2]
    const float* anchors = (const float*)d_in[2];   // [A, 4]
    float* out = (float*)d_out;

    const int A = in_sizes[2] / 4;
    int B = in_sizes[0] / (GMAX * 5);
    if (B > BMAX) B = BMAX;

    ssd_prep_kernel<<<B, 32>>>(gt, cls);
    dim3 grid((A + NTHR * ANCH - 1) / (NTHR * ANCH), B);
    ssd_target_kernel<<<grid, NTHR>>>(anchors, out, B, A);
}

// round 12
// speedup vs baseline: 1.0633x; 1.0633x over previous
#include <cuda_runtime.h>
#include <cstdint>

#define GMAX 64
#define ANCH 2
#define NTHR 128

__global__ void __launch_bounds__(NTHR, 14)
ssd_target_kernel(const float* __restrict__ gt,
                  const int*   __restrict__ cls,
                  const float* __restrict__ anchors,
                  float*       __restrict__ out,
                  int B, int A)
{
    __shared__ float4 s_box [GMAX];                    // y1,x1,y2,x2
    __shared__ float4 s_meta[GMAX];                    // gcy,gcx,log2(gh),log2(gw)
    __shared__ __align__(8) float s_area[GMAX];
    __shared__ float  s_cls [GMAX];
    __shared__ int    s_wcnt[2];                       // per-warp valid counts
    __shared__ int    s_cnt;                           // padded count (multiple of 2)

    const int lane = threadIdx.x & 31;
    const int wid  = threadIdx.x >> 5;
    const int b    = blockIdx.y;                       // one batch per block row

    // ---- 2-warp order-preserving compaction (warp w scans GTs 32w..32w+31) ----
    unsigned mval = 0; int myc = 0;
    float y1, x1, y2, x2;
    if (wid < 2) {
        const int g = wid * 32 + lane;
        const float* gp = gt + (size_t)(b * GMAX + g) * 5;
        y1 = gp[0]; x1 = gp[1]; y2 = gp[2]; x2 = gp[3];
        bool valid = (gp[4] != 0.0f);
        mval = __ballot_sync(0xffffffffu, valid);
        myc  = __popc(mval);
        if (lane == 0) s_wcnt[wid] = myc;
    }
    __syncthreads();
    if (wid < 2) {
        const int c0   = s_wcnt[0];
        const int base = (wid == 1) ? c0 : 0;
        const bool valid = (mval >> lane) & 1u;
        if (valid) {
            const int pos = base + __popc(mval & ((1u << lane) - 1u));
            s_box [pos] = make_float4(y1, x1, y2, x2);
            s_area[pos] = __fmul_rn(__fsub_rn(x2, x1), __fsub_rn(y2, y1));
            s_meta[pos] = make_float4((y2 + y1) * 0.5f, (x2 + x1) * 0.5f,
                                      __log2f(y2 - y1), __log2f(x2 - x1));
            s_cls [pos] = (float)cls[(size_t)(b * GMAX + wid * 32 + lane) * 2];
        }
        if (wid == 0 && lane == 0) {
            int cnt = c0 + s_wcnt[1];
            if (cnt == 0) {
                // reference: argmax over all -1 == index 0; deltas from raw gt[0]
                const float* gp = gt + (size_t)(b * GMAX) * 5;
                float ry1 = gp[0], rx1 = gp[1], ry2 = gp[2], rx2 = gp[3];
                s_box [0] = make_float4(ry1, rx1, ry2, rx2);
                s_area[0] = __fmul_rn(__fsub_rn(rx2, rx1), __fsub_rn(ry2, ry1));
                s_meta[0] = make_float4((ry2 + ry1) * 0.5f, (rx2 + rx1) * 0.5f,
                                        __log2f(ry2 - ry1), __log2f(rx2 - rx1));
                s_cls [0] = (float)cls[(size_t)(b * GMAX) * 2];
                cnt = 1;
            }
            // pad to multiple of 2 with a never-win dummy (inter==0, area==0)
            const int cnt_pad = (cnt + 1) & ~1;
            if (cnt_pad != cnt) {
                s_box [cnt] = make_float4(0.0f, 0.0f, 0.0f, 0.0f);
                s_area[cnt] = 0.0f;
                s_cls [cnt] = 0.0f;
                s_meta[cnt] = make_float4(0.0f, 0.0f, 0.0f, 0.0f);
            }
            s_cnt = cnt_pad;
        }
    }
    __syncthreads();

    const int a0 = blockIdx.x * (NTHR * ANCH) + threadIdx.x;
    const int a1 = a0 + NTHR;
    if (a0 >= A) return;
    const bool has1 = (a1 < A);

    const float4 an0 = __ldg(reinterpret_cast<const float4*>(anchors) + a0);
    const float4 an1 = has1 ? __ldg(reinterpret_cast<const float4*>(anchors) + a1) : an0;
    const float area0 = __fmul_rn(__fsub_rn(an0.w, an0.y), __fsub_rn(an0.z, an0.x));
    const float area1 = __fmul_rn(__fsub_rn(an1.w, an1.y), __fsub_rn(an1.z, an1.x));

    const int cntp = s_cnt;

    // Division/union-free argmax:
    //   iou_j > iou_b  <=>  inter_j * S_b > inter_b * S_j,  S = area_gt + area_an
    // max(0,x)==__saturatef(x) (extents < 1 -> .SAT folds into the FADD).
    // Dummies (inter=0, area=0) never beat a real entry; real entry 0 beats
    // the -1 sentinel even at inter==0.
    float bi0 = -1.0f, bS0 = 0.0f; int bj0 = 0;   // sentinel: iou = -1/(0-(-1)) = -1
    float bi1 = -1.0f, bS1 = 0.0f; int bj1 = 0;

    #define PAIR(g4, ag, jj)                                                        \
        {                                                                           \
            float iw0 = __saturatef(__fsub_rn(fminf((g4).w, an0.w),                 \
                                              fmaxf((g4).y, an0.y)));               \
            float ih0 = __saturatef(__fsub_rn(fminf((g4).z, an0.z),                 \
                                              fmaxf((g4).x, an0.x)));               \
            float in0 = __fmul_rn(iw0, ih0);                                        \
            float Sv0 = __fadd_rn((ag), area0);                                     \
            bool bt0 = __fmul_rn(in0, bS0) > __fmul_rn(bi0, Sv0);                   \
            bi0 = bt0 ? in0 : bi0;  bS0 = bt0 ? Sv0 : bS0;  bj0 = bt0 ? (jj) : bj0; \
            float iw1 = __saturatef(__fsub_rn(fminf((g4).w, an1.w),                 \
                                              fmaxf((g4).y, an1.y)));               \
            float ih1 = __saturatef(__fsub_rn(fminf((g4).z, an1.z),                 \
                                              fmaxf((g4).x, an1.x)));               \
            float in1 = __fmul_rn(iw1, ih1);                                        \
            float Sv1 = __fadd_rn((ag), area1);                                     \
            bool bt1 = __fmul_rn(in1, bS1) > __fmul_rn(bi1, Sv1);                   \
            bi1 = bt1 ? in1 : bi1;  bS1 = bt1 ? Sv1 : bS1;  bj1 = bt1 ? (jj) : bj1; \
        }

    for (int j = 0; j < cntp; j += 2) {     // cntp multiple of 2: no remainder
        const float2 a2 = *reinterpret_cast<const float2*>(s_area + j);
        const float4 g0 = s_box[j + 0];
        const float4 g1 = s_box[j + 1];
        PAIR(g0, a2.x, j + 0)
        PAIR(g1, a2.y, j + 1)
    }
    #undef PAIR

    const int N = B * A;
    float4* out4 = reinterpret_cast<float4*>(out);  // deltas  [0, 4N)
    float*  outc = out + 4 * (size_t)N;             // classes [4N, 5N)
    float*  outt = out + 5 * (size_t)N;             // tags    [5N, 6N)
    const float KLOG = 3.4657359027997265f;         // ln(2)/0.2 (folds /0.2 BBOX_STD)
    const int row = b * A;

    // ---- epilogue anchor 0 (tag path exact; delta path fast-approx, tol 1e-3) ----
    {
        const float iou_max = __fdiv_rn(bi0, __fsub_rn(bS0, bi0)); // u = S - inter
        const float tagv = (iou_max >= 0.5f) ? 1.0f
                          : ((iou_max < 0.4f) ? -1.0f : 0.0f);
        const float4 mt = s_meta[bj0];
        const float ah = an0.z - an0.x, aw = an0.w - an0.y;
        const float acy = (an0.z + an0.x) * 0.5f, acx = (an0.w + an0.y) * 0.5f;
        const float dy = (mt.x - acy) * __fdividef(10.0f, ah);
        const float dx = (mt.y - acx) * __fdividef(10.0f, aw);
        const float dh = (mt.z - __log2f(ah)) * KLOG;
        const float dw = (mt.w - __log2f(aw)) * KLOG;
        const int idx = row + a0;
        out4[idx] = make_float4(dy, dx, dh, dw);
        outc[idx] = s_cls[bj0];
        outt[idx] = tagv;
    }
    // ---- epilogue anchor 1 ----
    if (has1) {
        const float iou_max = __fdiv_rn(bi1, __fsub_rn(bS1, bi1));
        const float tagv = (iou_max >= 0.5f) ? 1.0f
                          : ((iou_max < 0.4f) ? -1.0f : 0.0f);
        const float4 mt = s_meta[bj1];
        const float ah = an1.z - an1.x, aw = an1.w - an1.y;
        const float acy = (an1.z + an1.x) * 0.5f, acx = (an1.w + an1.y) * 0.5f;
        const float dy = (mt.x - acy) * __fdividef(10.0f, ah);
        const float dx = (mt.y - acx) * __fdividef(10.0f, aw);
        const float dh = (mt.z - __log2f(ah)) * KLOG;
        const float dw = (mt.w - __log2f(aw)) * KLOG;
        const int idx = row + a1;
        out4[idx] = make_float4(dy, dx, dh, dw);
        outc[idx] = s_cls[bj1];
        outt[idx] = tagv;
    }
}

extern "C" void kernel_launch(void* const* d_in, const int* in_sizes, int n_in,
                              void* d_out, int out_size)
{
    const float* gt      = (const float*)d_in[0];   // [B, 64, 5]
    const int*   cls     = (const int*)  d_in[1];   // [B, 64, 2]
    const float* anchors = (const float*)d_in[2];   // [A, 4]
    float* out = (float*)d_out;

    const int A = in_sizes[2] / 4;
    const int B = in_sizes[0] / (GMAX * 5);

    dim3 grid((A + NTHR * ANCH - 1) / (NTHR * ANCH), B);
    ssd_target_kernel<<<grid, NTHR>>>(gt, cls, anchors, out, B, A);
}

// round 13
// speedup vs baseline: 1.0649x; 1.0015x over previous
#include <cuda_runtime.h>
#include <cstdint>

#define GMAX 64
#define ANCH 4
#define NTHR 128

__global__ void __launch_bounds__(NTHR, 8)
ssd_target_kernel(const float* __restrict__ gt,
                  const int*   __restrict__ cls,
                  const float* __restrict__ anchors,
                  float*       __restrict__ out,
                  int B, int A)
{
    __shared__ float4 s_box [GMAX];                    // y1,x1,y2,x2
    __shared__ float4 s_meta[GMAX];                    // gcy,gcx,log2(gh),log2(gw)
    __shared__ __align__(8) float s_area[GMAX];
    __shared__ float  s_cls [GMAX];
    __shared__ int    s_wcnt[2];
    __shared__ int    s_cnt;                           // padded count (multiple of 2)

    const int lane = threadIdx.x & 31;
    const int wid  = threadIdx.x >> 5;
    const int b    = blockIdx.y;                       // one batch per block row

    // ---- 2-warp order-preserving compaction (warp w scans GTs 32w..32w+31) ----
    unsigned mval = 0;
    float y1, x1, y2, x2;
    if (wid < 2) {
        const int g = wid * 32 + lane;
        const float* gp = gt + (size_t)(b * GMAX + g) * 5;
        y1 = gp[0]; x1 = gp[1]; y2 = gp[2]; x2 = gp[3];
        bool valid = (gp[4] != 0.0f);
        mval = __ballot_sync(0xffffffffu, valid);
        if (lane == 0) s_wcnt[wid] = __popc(mval);
    }
    __syncthreads();
    if (wid < 2) {
        const int c0   = s_wcnt[0];
        const int base = (wid == 1) ? c0 : 0;
        const bool valid = (mval >> lane) & 1u;
        if (valid) {
            const int pos = base + __popc(mval & ((1u << lane) - 1u));
            s_box [pos] = make_float4(y1, x1, y2, x2);
            s_area[pos] = __fmul_rn(__fsub_rn(x2, x1), __fsub_rn(y2, y1));
            s_meta[pos] = make_float4((y2 + y1) * 0.5f, (x2 + x1) * 0.5f,
                                      __log2f(y2 - y1), __log2f(x2 - x1));
            s_cls [pos] = (float)cls[(size_t)(b * GMAX + wid * 32 + lane) * 2];
        }
        if (wid == 0 && lane == 0) {
            int cnt = c0 + s_wcnt[1];
            if (cnt == 0) {
                // reference: argmax over all -1 == index 0; deltas from raw gt[0]
                const float* gp = gt + (size_t)(b * GMAX) * 5;
                float ry1 = gp[0], rx1 = gp[1], ry2 = gp[2], rx2 = gp[3];
                s_box [0] = make_float4(ry1, rx1, ry2, rx2);
                s_area[0] = __fmul_rn(__fsub_rn(rx2, rx1), __fsub_rn(ry2, ry1));
                s_meta[0] = make_float4((ry2 + ry1) * 0.5f, (rx2 + rx1) * 0.5f,
                                        __log2f(ry2 - ry1), __log2f(rx2 - rx1));
                s_cls [0] = (float)cls[(size_t)(b * GMAX) * 2];
                cnt = 1;
            }
            const int cnt_pad = (cnt + 1) & ~1;  // pad to even with never-win dummy
            if (cnt_pad != cnt) {
                s_box [cnt] = make_float4(0.0f, 0.0f, 0.0f, 0.0f);
                s_area[cnt] = 0.0f;
                s_cls [cnt] = 0.0f;
                s_meta[cnt] = make_float4(0.0f, 0.0f, 0.0f, 0.0f);
            }
            s_cnt = cnt_pad;
        }
    }
    __syncthreads();

    const int abase = blockIdx.x * (NTHR * ANCH) + threadIdx.x;
    if (abase >= A) return;

    float4 an[ANCH];
    float  area[ANCH];
    #pragma unroll
    for (int k = 0; k < ANCH; ++k) {
        int ak = abase + k * NTHR;
        an[k] = __ldg(reinterpret_cast<const float4*>(anchors) + min(ak, A - 1));
        area[k] = __fmul_rn(__fsub_rn(an[k].w, an[k].y), __fsub_rn(an[k].z, an[k].x));
    }

    const int cntp = s_cnt;

    // Division/union-free argmax:
    //   iou_j > iou_b  <=>  inter_j * S_b > inter_b * S_j,  S = area_gt + area_an
    // max(0,x)==__saturatef(x) (extents < 1 -> .SAT folds into the FADD).
    // Dummies (inter=0, area=0) never beat a real entry; real entry 0 beats
    // the -1 sentinel even at inter==0.
    float bi[ANCH], bS[ANCH];
    int   bj[ANCH];
    #pragma unroll
    for (int k = 0; k < ANCH; ++k) { bi[k] = -1.0f; bS[k] = 0.0f; bj[k] = 0; }

    for (int j = 0; j < cntp; j += 2) {     // cntp multiple of 2: no remainder
        const float2 a2 = *reinterpret_cast<const float2*>(s_area + j);
        const float4 g0 = s_box[j + 0];
        const float4 g1 = s_box[j + 1];
        #pragma unroll
        for (int k = 0; k < ANCH; ++k) {
            // GT j
            {
                float iw = __saturatef(__fsub_rn(fminf(g0.w, an[k].w), fmaxf(g0.y, an[k].y)));
                float ih = __saturatef(__fsub_rn(fminf(g0.z, an[k].z), fmaxf(g0.x, an[k].x)));
                float in = __fmul_rn(iw, ih);
                float Sv = __fadd_rn(a2.x, area[k]);
                bool bt = __fmul_rn(in, bS[k]) > __fmul_rn(bi[k], Sv);
                bi[k] = bt ? in : bi[k];  bS[k] = bt ? Sv : bS[k];  bj[k] = bt ? j : bj[k];
            }
            // GT j+1
            {
                float iw = __saturatef(__fsub_rn(fminf(g1.w, an[k].w), fmaxf(g1.y, an[k].y)));
                float ih = __saturatef(__fsub_rn(fminf(g1.z, an[k].z), fmaxf(g1.x, an[k].x)));
                float in = __fmul_rn(iw, ih);
                float Sv = __fadd_rn(a2.y, area[k]);
                bool bt = __fmul_rn(in, bS[k]) > __fmul_rn(bi[k], Sv);
                bi[k] = bt ? in : bi[k];  bS[k] = bt ? Sv : bS[k];  bj[k] = bt ? (j + 1) : bj[k];
            }
        }
    }

    const int N = B * A;
    float4* out4 = reinterpret_cast<float4*>(out);  // deltas  [0, 4N)
    float*  outc = out + 4 * (size_t)N;             // classes [4N, 5N)
    float*  outt = out + 5 * (size_t)N;             // tags    [5N, 6N)
    const float KLOG = 3.4657359027997265f;         // ln(2)/0.2 (folds /0.2 BBOX_STD)
    const int row = b * A;

    #pragma unroll
    for (int k = 0; k < ANCH; ++k) {
        const int ak = abase + k * NTHR;
        if (ak >= A) break;
        // tag path exact: u = S - inter with reference rounding, then exact divide
        const float iou_max = __fdiv_rn(bi[k], __fsub_rn(bS[k], bi[k]));
        const float tagv = (iou_max >= 0.5f) ? 1.0f
                          : ((iou_max < 0.4f) ? -1.0f : 0.0f);
        const float4 mt = s_meta[bj[k]];
        const float ah = an[k].z - an[k].x, aw = an[k].w - an[k].y;
        const float acy = (an[k].z + an[k].x) * 0.5f, acx = (an[k].w + an[k].y) * 0.5f;
        const float dy = (mt.x - acy) * __fdividef(10.0f, ah);
        const float dx = (mt.y - acx) * __fdividef(10.0f, aw);
        const float dh = (mt.z - __log2f(ah)) * KLOG;
        const float dw = (mt.w - __log2f(aw)) * KLOG;
        const int idx = row + ak;
        out4[idx] = make_float4(dy, dx, dh, dw);
        outc[idx] = s_cls[bj[k]];
        outt[idx] = tagv;
    }
}

extern "C" void kernel_launch(void* const* d_in, const int* in_sizes, int n_in,
                              void* d_out, int out_size)
{
    const float* gt      = (const float*)d_in[0];   // [B, 64, 5]
    const int*   cls     = (const int*)  d_in[1];   // [B, 64, 2]
    const float* anchors = (const float*)d_in[2];   // [A, 4]
    float* out = (float*)d_out;

    const int A = in_sizes[2] / 4;
    const int B = in_sizes[0] / (GMAX * 5);

    dim3 grid((A + NTHR * ANCH - 1) / (NTHR * ANCH), B);
    ssd_target_kernel<<<grid, NTHR>>>(gt, cls, anchors, out, B, A);
}